// round 4
// baseline (speedup 1.0000x reference)
#include <cuda_runtime.h>
#include <cuda_bf16.h>

// Problem constants (fixed by the dataset)
#define Bc   4
#define Cc   16
#define Hc   256
#define Wc   256
#define HWc  (Hc * Wc)
#define Coc  16
#define Kc   9
#define INV_N (1.0f / (float)(Bc * Coc * HWc))

// Tiling: 32x8 pixel tile, 256 threads, 1 pixel/thread, 2 channel phases
#define TILE_W 32
#define TILE_H 8
#define PAD    6
#define ROWS   (TILE_H + 2 * PAD)     // 20
#define COLS   (TILE_W + 2 * PAD)     // 44
#define NSITES (ROWS * COLS)          // 880
#define CPP    8                      // channels per phase
#define SITE_STRIDE 12                // floats per site (8 ch + 4 pad): 48B, 16B-aligned, bank-spread
#define SKER_OFF (NSITES * SITE_STRIDE)          // 10560 floats
#define SMEM_FLOATS (SKER_OFF + Kc * Cc * Coc)   // + 2304 = 12864
#define SMEM_BYTES  (SMEM_FLOATS * 4)            // 51456 B

typedef unsigned long long ull;

__device__ __forceinline__ ull pack2(float a, float b) {
    ull r; asm("mov.b64 %0, {%1, %2};" : "=l"(r) : "f"(a), "f"(b)); return r;
}
__device__ __forceinline__ void ffma2(ull& d, ull a, ull b) {
    asm("fma.rn.f32x2 %0, %1, %2, %0;" : "+l"(d) : "l"(a), "l"(b));
}
__device__ __forceinline__ void unpack2(ull v, float& lo, float& hi) {
    asm("mov.b64 {%0, %1}, %2;" : "=f"(lo), "=f"(hi) : "l"(v));
}

__global__ void zero_out_kernel(float* out) {
    if (threadIdx.x == 0) out[0] = 0.0f;
}

extern __shared__ float smem[];

__global__ __launch_bounds__(256, 3) void dcn_loss_kernel(
    const float* __restrict__ offsets,  // [B, 18, H, W]
    const float* __restrict__ input,    // [B, 16, H, W]
    const float* __restrict__ ker,      // [16, 16, 3, 3]
    const float* __restrict__ target,   // [B, 16, H, W]
    float* __restrict__ out)
{
    const int tid = threadIdx.x;
    const int b   = blockIdx.z;
    const int rowBase = blockIdx.y * TILE_H;
    const int colBase = blockIdx.x * TILE_W;
    const int rowLo = rowBase - PAD;
    const int colLo = colBase - PAD;

    const float* inB = input + b * Cc * HWc;
    float* sIn = smem;
    float* skw = smem + SKER_OFF;

    // ---- Stage weights once: skw[(kk*16 + c)*16 + o] ----
    for (int i = tid; i < Kc * Cc * Coc; i += 256) {
        const int o  = i & 15;
        const int ck = i >> 4;          // kk*16 + c
        const int kk = ck >> 4;
        const int c  = ck & 15;
        skw[i] = ker[o * (Cc * Kc) + c * Kc + kk];
    }

    // ---- Per-thread pixel ----
    const int lane = tid & 31;
    const int r    = tid >> 5;
    const int wpx  = colBase + lane;
    const int hpx  = rowBase + r;
    const int hw   = hpx * Wc + wpx;
    const float* offP = offsets + b * 2 * Kc * HWc + hw;

    ull acc2[8];
    #pragma unroll
    for (int j = 0; j < 8; j++) acc2[j] = 0ull;

    #pragma unroll
    for (int phase = 0; phase < 2; phase++) {
        const int c0 = phase * CPP;

        // ---- Stage this phase's 8 channels (zeros outside image) ----
        for (int i = tid; i < NSITES; i += 256) {
            const int ry = i / COLS;
            const int rx = i - ry * COLS;
            const int gy = rowLo + ry;
            const int gx = colLo + rx;
            const bool ok = ((unsigned)gy < Hc) && ((unsigned)gx < Wc);
            const float* src = inB + c0 * HWc + gy * Wc + gx;
            float* dst = sIn + i * SITE_STRIDE;
            #pragma unroll
            for (int q = 0; q < 2; q++) {
                float4 v;
                v.x = ok ? __ldg(src + (4 * q + 0) * HWc) : 0.0f;
                v.y = ok ? __ldg(src + (4 * q + 1) * HWc) : 0.0f;
                v.z = ok ? __ldg(src + (4 * q + 2) * HWc) : 0.0f;
                v.w = ok ? __ldg(src + (4 * q + 3) * HWc) : 0.0f;
                *(float4*)(dst + 4 * q) = v;
            }
        }
        __syncthreads();

        for (int kk = 0; kk < Kc; kk++) {
            const int kr = kk / 3;
            const int kc = kk - 3 * kr;

            const float dy = __ldg(offP + (2 * kk) * HWc);
            const float dx = __ldg(offP + (2 * kk + 1) * HWc);
            const float y = dy + (float)(hpx - 1 + kr);
            const float x = dx + (float)(wpx - 1 + kc);

            const float y0f = floorf(y), x0f = floorf(x);
            const float wy = y - y0f, wx = x - x0f;
            const int ry0 = (int)y0f - rowLo;
            const int rx0 = (int)x0f - colLo;

            if (((unsigned)ry0 <= (ROWS - 2)) && ((unsigned)rx0 <= (COLS - 2))) {
                const float w00 = (1.0f - wy) * (1.0f - wx);
                const float w01 = (1.0f - wy) * wx;
                const float w10 = wy          * (1.0f - wx);
                const float w11 = wy          * wx;
                const float* pa = sIn + (ry0 * COLS + rx0) * SITE_STRIDE;

                #pragma unroll
                for (int q = 0; q < 2; q++) {
                    const float4 a00 = *(const float4*)(pa + 4 * q);
                    const float4 a01 = *(const float4*)(pa + SITE_STRIDE + 4 * q);
                    const float4 a10 = *(const float4*)(pa + COLS * SITE_STRIDE + 4 * q);
                    const float4 a11 = *(const float4*)(pa + (COLS + 1) * SITE_STRIDE + 4 * q);
                    float sv[4];
                    sv[0] = w00 * a00.x + w01 * a01.x + w10 * a10.x + w11 * a11.x;
                    sv[1] = w00 * a00.y + w01 * a01.y + w10 * a10.y + w11 * a11.y;
                    sv[2] = w00 * a00.z + w01 * a01.z + w10 * a10.z + w11 * a11.z;
                    sv[3] = w00 * a00.w + w01 * a01.w + w10 * a10.w + w11 * a11.w;

                    #pragma unroll
                    for (int j = 0; j < 4; j++) {
                        const ull sx = pack2(sv[j], sv[j]);
                        const ulonglong2* kw =
                            (const ulonglong2*)(skw + ((kk * Cc + c0 + 4 * q + j) << 4));
                        const ulonglong2 k0 = kw[0], k1 = kw[1], k2 = kw[2], k3 = kw[3];
                        ffma2(acc2[0], sx, k0.x); ffma2(acc2[1], sx, k0.y);
                        ffma2(acc2[2], sx, k1.x); ffma2(acc2[3], sx, k1.y);
                        ffma2(acc2[4], sx, k2.x); ffma2(acc2[5], sx, k2.y);
                        ffma2(acc2[6], sx, k3.x); ffma2(acc2[7], sx, k3.y);
                    }
                }
            } else {
                // Rare exact fallback from global (validity-masked, clamped idx)
                const int y0 = (int)y0f, x0 = (int)x0f;
                const int y1 = y0 + 1, x1 = x0 + 1;
                const bool vy0 = ((unsigned)y0 < Hc), vy1 = ((unsigned)y1 < Hc);
                const bool vx0 = ((unsigned)x0 < Wc), vx1 = ((unsigned)x1 < Wc);
                const float w00 = (1.0f - wy) * (1.0f - wx) * (float)(vy0 && vx0);
                const float w01 = (1.0f - wy) * wx          * (float)(vy0 && vx1);
                const float w10 = wy          * (1.0f - wx) * (float)(vy1 && vx0);
                const float w11 = wy          * wx          * (float)(vy1 && vx1);
                const int cy0 = min(max(y0, 0), Hc - 1), cy1 = min(max(y1, 0), Hc - 1);
                const int cx0 = min(max(x0, 0), Wc - 1), cx1 = min(max(x1, 0), Wc - 1);
                const int i00 = cy0 * Wc + cx0, i01 = cy0 * Wc + cx1;
                const int i10 = cy1 * Wc + cx0, i11 = cy1 * Wc + cx1;
                #pragma unroll
                for (int cc = 0; cc < CPP; cc++) {
                    const int c = c0 + cc;
                    const float* ic = inB + c * HWc;
                    const float s = w00 * __ldg(ic + i00) + w01 * __ldg(ic + i01)
                                  + w10 * __ldg(ic + i10) + w11 * __ldg(ic + i11);
                    const ull sx = pack2(s, s);
                    const ulonglong2* kw = (const ulonglong2*)(skw + ((kk * Cc + c) << 4));
                    const ulonglong2 k0 = kw[0], k1 = kw[1], k2 = kw[2], k3 = kw[3];
                    ffma2(acc2[0], sx, k0.x); ffma2(acc2[1], sx, k0.y);
                    ffma2(acc2[2], sx, k1.x); ffma2(acc2[3], sx, k1.y);
                    ffma2(acc2[4], sx, k2.x); ffma2(acc2[5], sx, k2.y);
                    ffma2(acc2[6], sx, k3.x); ffma2(acc2[7], sx, k3.y);
                }
            }
        }
        __syncthreads();   // before next phase overwrites the tile
    }

    // ---- Squared error vs target ----
    const float* tgt = target + b * Coc * HWc + hw;
    float local = 0.0f;
    #pragma unroll
    for (int j = 0; j < 8; j++) {
        float lo, hi;
        unpack2(acc2[j], lo, hi);
        const float d0 = lo - __ldg(tgt + (2 * j) * HWc);
        const float d1 = hi - __ldg(tgt + (2 * j + 1) * HWc);
        local += d0 * d0 + d1 * d1;
    }

    // ---- Warp + block reduce, one atomic per block ----
    #pragma unroll
    for (int s = 16; s > 0; s >>= 1)
        local += __shfl_xor_sync(0xFFFFFFFFu, local, s);

    __shared__ float red[8];
    if ((tid & 31) == 0) red[tid >> 5] = local;
    __syncthreads();
    if (tid < 8) {
        float v = red[tid];
        #pragma unroll
        for (int s = 4; s > 0; s >>= 1)
            v += __shfl_xor_sync(0xFFu, v, s);
        if (tid == 0) atomicAdd(out, v * INV_N);
    }
}

extern "C" void kernel_launch(void* const* d_in, const int* in_sizes, int n_in,
                              void* d_out, int out_size) {
    const float* offsets = (const float*)d_in[0];
    const float* input   = (const float*)d_in[1];
    const float* ker     = (const float*)d_in[2];
    const float* target  = (const float*)d_in[3];
    float* out = (float*)d_out;

    static bool attr_set = false;
    if (!attr_set) {
        cudaFuncSetAttribute(dcn_loss_kernel,
                             cudaFuncAttributeMaxDynamicSharedMemorySize,
                             SMEM_BYTES);
        attr_set = true;
    }

    zero_out_kernel<<<1, 32>>>(out);

    dim3 grid(Wc / TILE_W, Hc / TILE_H, Bc);   // 8 x 32 x 4 = 1024 blocks
    dcn_loss_kernel<<<grid, 256, SMEM_BYTES>>>(offsets, input, ker, target, out);
}

// round 5
// speedup vs baseline: 1.3771x; 1.3771x over previous
#include <cuda_runtime.h>
#include <cuda_fp16.h>
#include <cuda_bf16.h>

// Problem constants (fixed by the dataset)
#define Bc   4
#define Cc   16
#define Hc   256
#define Wc   256
#define HWc  (Hc * Wc)
#define Coc  16
#define Kc   9
#define INV_N (1.0f / (float)(Bc * Coc * HWc))

// Tiling: 32x16 pixel tile, 256 threads, 2 pixels/thread (rows r and r+8)
#define TILE_W 32
#define TILE_H 16
#define PAD    6
#define ROWS   (TILE_H + 2 * PAD)     // 28
#define COLS   (TILE_W + 2 * PAD)     // 44
#define NSITES (ROWS * COLS)          // 1232
// fp16 tile: 16 halves per site = 32 bytes = 2 uint4
#define SIN_BYTES   (NSITES * 32)                // 39424
#define SKER_FLOATS (Kc * Cc * Coc)              // 2304
#define SMEM_BYTES  (SIN_BYTES + SKER_FLOATS * 4) // 48640

typedef unsigned long long ull;

__device__ __forceinline__ ull pack2(float a, float b) {
    ull r; asm("mov.b64 %0, {%1, %2};" : "=l"(r) : "f"(a), "f"(b)); return r;
}
__device__ __forceinline__ void ffma2(ull& d, ull a, ull b) {
    asm("fma.rn.f32x2 %0, %1, %2, %0;" : "+l"(d) : "l"(a), "l"(b));
}
__device__ __forceinline__ void unpack2(ull v, float& lo, float& hi) {
    asm("mov.b64 {%0, %1}, %2;" : "=f"(lo), "=f"(hi) : "l"(v));
}

__global__ void zero_out_kernel(float* out) {
    if (threadIdx.x == 0) out[0] = 0.0f;
}

extern __shared__ float smem[];

__global__ __launch_bounds__(256, 2) void dcn_loss_kernel(
    const float* __restrict__ offsets,  // [B, 18, H, W]
    const float* __restrict__ input,    // [B, 16, H, W]
    const float* __restrict__ ker,      // [16, 16, 3, 3]
    const float* __restrict__ target,   // [B, 16, H, W]
    float* __restrict__ out)
{
    const int tid = threadIdx.x;
    const int b   = blockIdx.z;
    const int rowBase = blockIdx.y * TILE_H;
    const int colBase = blockIdx.x * TILE_W;
    const int rowLo = rowBase - PAD;
    const int colLo = colBase - PAD;

    const float* inB = input + b * Cc * HWc;
    uint4* sIn = (uint4*)smem;                       // 2 uint4 per site
    float* skw = (float*)((char*)smem + SIN_BYTES);  // fp32 weights

    // ---- Stage input tile as fp16, site-major (zeros outside image) ----
    for (int i = tid; i < NSITES; i += 256) {
        const int ry = i / COLS;
        const int rx = i - ry * COLS;
        const int gy = rowLo + ry;
        const int gx = colLo + rx;
        const bool ok = ((unsigned)gy < Hc) && ((unsigned)gx < Wc);
        const float* src = inB + gy * Wc + gx;
        __half2 h[8];
        #pragma unroll
        for (int j = 0; j < 8; j++) {
            float v0 = ok ? __ldg(src + (2 * j) * HWc)     : 0.0f;
            float v1 = ok ? __ldg(src + (2 * j + 1) * HWc) : 0.0f;
            h[j] = __floats2half2_rn(v0, v1);
        }
        sIn[2 * i]     = *(const uint4*)&h[0];
        sIn[2 * i + 1] = *(const uint4*)&h[4];
    }

    // ---- Stage weights: skw[(kk*16 + c)*16 + o]  (fp32) ----
    for (int i = tid; i < Kc * Cc * Coc; i += 256) {
        const int o  = i & 15;
        const int ck = i >> 4;          // kk*16 + c
        const int kk = ck >> 4;
        const int c  = ck & 15;
        skw[i] = ker[o * (Cc * Kc) + c * Kc + kk];
    }
    __syncthreads();

    // ---- Two pixels per thread ----
    const int lane = tid & 31;
    const int r    = tid >> 5;
    const int wpx  = colBase + lane;
    const int ha   = rowBase + r;
    const int hb   = ha + 8;
    const int hwa  = ha * Wc + wpx;
    const int hwb  = hb * Wc + wpx;

    const float* offA = offsets + b * 2 * Kc * HWc + hwa;
    const float* offBp = offsets + b * 2 * Kc * HWc + hwb;

    ull acc2a[8], acc2b[8];
    #pragma unroll
    for (int j = 0; j < 8; j++) { acc2a[j] = 0ull; acc2b[j] = 0ull; }

    // Rare exact fallback from global (validity-masked, clamped idx)
    auto tap_generic = [&](float y, float x, ull* acc2, int kk) {
        const float y0f = floorf(y), x0f = floorf(x);
        const float wy = y - y0f, wx = x - x0f;
        const int y0 = (int)y0f, x0 = (int)x0f;
        const int y1 = y0 + 1, x1 = x0 + 1;
        const bool vy0 = ((unsigned)y0 < Hc), vy1 = ((unsigned)y1 < Hc);
        const bool vx0 = ((unsigned)x0 < Wc), vx1 = ((unsigned)x1 < Wc);
        const float w00 = (1.0f - wy) * (1.0f - wx) * (float)(vy0 && vx0);
        const float w01 = (1.0f - wy) * wx          * (float)(vy0 && vx1);
        const float w10 = wy          * (1.0f - wx) * (float)(vy1 && vx0);
        const float w11 = wy          * wx          * (float)(vy1 && vx1);
        const int cy0 = min(max(y0, 0), Hc - 1), cy1 = min(max(y1, 0), Hc - 1);
        const int cx0 = min(max(x0, 0), Wc - 1), cx1 = min(max(x1, 0), Wc - 1);
        const int i00 = cy0 * Wc + cx0, i01 = cy0 * Wc + cx1;
        const int i10 = cy1 * Wc + cx0, i11 = cy1 * Wc + cx1;
        #pragma unroll
        for (int c = 0; c < Cc; c++) {
            const float* ic = inB + c * HWc;
            const float s = w00 * __ldg(ic + i00) + w01 * __ldg(ic + i01)
                          + w10 * __ldg(ic + i10) + w11 * __ldg(ic + i11);
            const ull sx = pack2(s, s);
            const ulonglong2* kw = (const ulonglong2*)(skw + ((kk * Cc + c) << 4));
            const ulonglong2 k0 = kw[0], k1 = kw[1], k2 = kw[2], k3 = kw[3];
            ffma2(acc2[0], sx, k0.x); ffma2(acc2[1], sx, k0.y);
            ffma2(acc2[2], sx, k1.x); ffma2(acc2[3], sx, k1.y);
            ffma2(acc2[4], sx, k2.x); ffma2(acc2[5], sx, k2.y);
            ffma2(acc2[6], sx, k3.x); ffma2(acc2[7], sx, k3.y);
        }
    };

    // Fast-path sampler: bilinear in packed half2, result -> fp32 s[16]
    auto sample16 = [&](int site, float wy, float wx, float* s) {
        const float w00 = (1.0f - wy) * (1.0f - wx);
        const float w01 = (1.0f - wy) * wx;
        const float w10 = wy          * (1.0f - wx);
        const float w11 = wy          * wx;
        const __half2 h00 = __float2half2_rn(w00);
        const __half2 h01 = __float2half2_rn(w01);
        const __half2 h10 = __float2half2_rn(w10);
        const __half2 h11 = __float2half2_rn(w11);

        const uint4* p = sIn + 2 * site;
        #pragma unroll
        for (int half4 = 0; half4 < 2; half4++) {        // channels 0-7, 8-15
            const uint4 a00 = p[half4];
            const uint4 a01 = p[2 + half4];                       // site+1
            const uint4 a10 = p[2 * COLS + half4];                // site+COLS
            const uint4 a11 = p[2 * COLS + 2 + half4];            // site+COLS+1
            const __half2* c00 = (const __half2*)&a00;
            const __half2* c01 = (const __half2*)&a01;
            const __half2* c10 = (const __half2*)&a10;
            const __half2* c11 = (const __half2*)&a11;
            #pragma unroll
            for (int j = 0; j < 4; j++) {
                __half2 v = __hmul2(c00[j], h00);
                v = __hfma2(c01[j], h01, v);
                v = __hfma2(c10[j], h10, v);
                v = __hfma2(c11[j], h11, v);
                const float2 f = __half22float2(v);
                s[half4 * 8 + 2 * j]     = f.x;
                s[half4 * 8 + 2 * j + 1] = f.y;
            }
        }
    };

    for (int kk = 0; kk < Kc; kk++) {
        const int kr = kk / 3;
        const int kc = kk - 3 * kr;

        const float dya = __ldg(offA + (2 * kk) * HWc);
        const float dxa = __ldg(offA + (2 * kk + 1) * HWc);
        const float dyb = __ldg(offBp + (2 * kk) * HWc);
        const float dxb = __ldg(offBp + (2 * kk + 1) * HWc);

        const float ya = dya + (float)(ha - 1 + kr);
        const float xa = dxa + (float)(wpx - 1 + kc);
        const float yb = dyb + (float)(hb - 1 + kr);
        const float xb = dxb + (float)(wpx - 1 + kc);

        const float ya0f = floorf(ya), xa0f = floorf(xa);
        const float yb0f = floorf(yb), xb0f = floorf(xb);
        const float wya = ya - ya0f, wxa = xa - xa0f;
        const float wyb = yb - yb0f, wxb = xb - xb0f;

        const int ry0a = (int)ya0f - rowLo, rx0a = (int)xa0f - colLo;
        const int ry0b = (int)yb0f - rowLo, rx0b = (int)xb0f - colLo;

        const bool fa = ((unsigned)ry0a <= (ROWS - 2)) && ((unsigned)rx0a <= (COLS - 2));
        const bool fb = ((unsigned)ry0b <= (ROWS - 2)) && ((unsigned)rx0b <= (COLS - 2));

        if (fa && fb) {
            float sa[16], sb[16];
            sample16(ry0a * COLS + rx0a, wya, wxa, sa);
            sample16(ry0b * COLS + rx0b, wyb, wxb, sb);

            const ulonglong2* kwBase = (const ulonglong2*)(skw + ((kk * Cc) << 4));
            #pragma unroll
            for (int c = 0; c < Cc; c++) {
                const ull sxa = pack2(sa[c], sa[c]);
                const ull sxb = pack2(sb[c], sb[c]);
                const ulonglong2* kw = kwBase + c * 4;
                const ulonglong2 k0 = kw[0], k1 = kw[1], k2 = kw[2], k3 = kw[3];
                ffma2(acc2a[0], sxa, k0.x); ffma2(acc2a[1], sxa, k0.y);
                ffma2(acc2a[2], sxa, k1.x); ffma2(acc2a[3], sxa, k1.y);
                ffma2(acc2a[4], sxa, k2.x); ffma2(acc2a[5], sxa, k2.y);
                ffma2(acc2a[6], sxa, k3.x); ffma2(acc2a[7], sxa, k3.y);
                ffma2(acc2b[0], sxb, k0.x); ffma2(acc2b[1], sxb, k0.y);
                ffma2(acc2b[2], sxb, k1.x); ffma2(acc2b[3], sxb, k1.y);
                ffma2(acc2b[4], sxb, k2.x); ffma2(acc2b[5], sxb, k2.y);
                ffma2(acc2b[6], sxb, k3.x); ffma2(acc2b[7], sxb, k3.y);
            }
        } else {
            tap_generic(ya, xa, acc2a, kk);
            tap_generic(yb, xb, acc2b, kk);
        }
    }

    // ---- Squared error vs target for both pixels ----
    const float* ta = target + b * Coc * HWc + hwa;
    const float* tb = target + b * Coc * HWc + hwb;
    float local = 0.0f;
    #pragma unroll
    for (int j = 0; j < 8; j++) {
        float lo, hi;
        unpack2(acc2a[j], lo, hi);
        float d0 = lo - __ldg(ta + (2 * j) * HWc);
        float d1 = hi - __ldg(ta + (2 * j + 1) * HWc);
        local += d0 * d0 + d1 * d1;
        unpack2(acc2b[j], lo, hi);
        d0 = lo - __ldg(tb + (2 * j) * HWc);
        d1 = hi - __ldg(tb + (2 * j + 1) * HWc);
        local += d0 * d0 + d1 * d1;
    }

    // ---- Warp + block reduce, one atomic per block ----
    #pragma unroll
    for (int s = 16; s > 0; s >>= 1)
        local += __shfl_xor_sync(0xFFFFFFFFu, local, s);

    __shared__ float red[8];
    if ((tid & 31) == 0) red[tid >> 5] = local;
    __syncthreads();
    if (tid < 8) {
        float v = red[tid];
        #pragma unroll
        for (int s = 4; s > 0; s >>= 1)
            v += __shfl_xor_sync(0xFFu, v, s);
        if (tid == 0) atomicAdd(out, v * INV_N);
    }
}

extern "C" void kernel_launch(void* const* d_in, const int* in_sizes, int n_in,
                              void* d_out, int out_size) {
    const float* offsets = (const float*)d_in[0];
    const float* input   = (const float*)d_in[1];
    const float* ker     = (const float*)d_in[2];
    const float* target  = (const float*)d_in[3];
    float* out = (float*)d_out;

    static bool attr_set = false;
    if (!attr_set) {
        cudaFuncSetAttribute(dcn_loss_kernel,
                             cudaFuncAttributeMaxDynamicSharedMemorySize,
                             SMEM_BYTES);
        attr_set = true;
    }

    zero_out_kernel<<<1, 32>>>(out);

    dim3 grid(Wc / TILE_W, Hc / TILE_H, Bc);   // 8 x 16 x 4 = 512 blocks
    dcn_loss_kernel<<<grid, 256, SMEM_BYTES>>>(offsets, input, ker, target, out);
}

// round 6
// speedup vs baseline: 1.5553x; 1.1294x over previous
#include <cuda_runtime.h>
#include <cuda_fp16.h>
#include <cuda_bf16.h>

// Problem constants (fixed by the dataset)
#define Bc   4
#define Cc   16
#define Hc   256
#define Wc   256
#define HWc  (Hc * Wc)
#define Coc  16
#define Kc   9
#define INV_N (1.0f / (float)(Bc * Coc * HWc))

// Tiling: 32x16 pixel tile, 256 threads, 2 pixels/thread (rows r and r+8)
#define TILE_W 32
#define TILE_H 16
#define PAD    6
#define ROWS   (TILE_H + 2 * PAD)     // 28
#define COLS   (TILE_W + 2 * PAD)     // 44
#define NSITES (ROWS * COLS)          // 1232
// fp16 tile: 16 halves per site = 32 bytes = 2 uint4
#define SIN_BYTES   (NSITES * 32)                   // 39424
#define SKER_H2     (Kc * Cc * Coc / 2)             // 1152 half2
#define SMEM_BYTES  (SIN_BYTES + SKER_H2 * 4)       // 44032 B

__global__ void zero_out_kernel(float* out) {
    if (threadIdx.x == 0) out[0] = 0.0f;
}

extern __shared__ float smem[];

__global__ __launch_bounds__(256, 2) void dcn_loss_kernel(
    const float* __restrict__ offsets,  // [B, 18, H, W]
    const float* __restrict__ input,    // [B, 16, H, W]
    const float* __restrict__ ker,      // [16, 16, 3, 3]
    const float* __restrict__ target,   // [B, 16, H, W]
    float* __restrict__ out)
{
    const int tid = threadIdx.x;
    const int b   = blockIdx.z;
    const int rowBase = blockIdx.y * TILE_H;
    const int colBase = blockIdx.x * TILE_W;
    const int rowLo = rowBase - PAD;
    const int colLo = colBase - PAD;

    const float* inB = input + b * Cc * HWc;
    uint4*   sIn  = (uint4*)smem;                         // 2 uint4 per site
    __half2* skwh = (__half2*)((char*)smem + SIN_BYTES);  // packed half2 weights

    // ---- Stage input tile as fp16, site-major (zeros outside image) ----
    for (int i = tid; i < NSITES; i += 256) {
        const int ry = i / COLS;
        const int rx = i - ry * COLS;
        const int gy = rowLo + ry;
        const int gx = colLo + rx;
        const bool ok = ((unsigned)gy < Hc) && ((unsigned)gx < Wc);
        const float* src = inB + gy * Wc + gx;
        __half2 h[8];
        #pragma unroll
        for (int j = 0; j < 8; j++) {
            float v0 = ok ? __ldg(src + (2 * j) * HWc)     : 0.0f;
            float v1 = ok ? __ldg(src + (2 * j + 1) * HWc) : 0.0f;
            h[j] = __floats2half2_rn(v0, v1);
        }
        sIn[2 * i]     = *(const uint4*)&h[0];
        sIn[2 * i + 1] = *(const uint4*)&h[4];
    }

    // ---- Stage weights: skwh[(kk*16 + c)*8 + j] = (w[o=2j], w[o=2j+1]) ----
    for (int i = tid; i < SKER_H2; i += 256) {
        const int j  = i & 7;           // output pair
        const int ck = i >> 3;          // kk*16 + c
        const int kk = ck >> 4;
        const int c  = ck & 15;
        const float w0 = ker[(2 * j)     * (Cc * Kc) + c * Kc + kk];
        const float w1 = ker[(2 * j + 1) * (Cc * Kc) + c * Kc + kk];
        skwh[i] = __floats2half2_rn(w0, w1);
    }
    __syncthreads();

    // ---- Two pixels per thread ----
    const int lane = tid & 31;
    const int r    = tid >> 5;
    const int wpx  = colBase + lane;
    const int ha   = rowBase + r;
    const int hb   = ha + 8;
    const int hwa  = ha * Wc + wpx;
    const int hwb  = hb * Wc + wpx;

    const float* offA  = offsets + b * 2 * Kc * HWc + hwa;
    const float* offBp = offsets + b * 2 * Kc * HWc + hwb;

    __half2 acc_a[8], acc_b[8];          // acc[j] holds outputs (2j, 2j+1)
    #pragma unroll
    for (int j = 0; j < 8; j++) {
        acc_a[j] = __float2half2_rn(0.0f);
        acc_b[j] = __float2half2_rn(0.0f);
    }

    // Accumulate one channel's replicated sample against its 8 weight-half2
    auto acc_channel = [&](__half2* acc, __half2 srep, const uint4 k0, const uint4 k1) {
        const __half2* ka = (const __half2*)&k0;
        const __half2* kb = (const __half2*)&k1;
        acc[0] = __hfma2(srep, ka[0], acc[0]);
        acc[1] = __hfma2(srep, ka[1], acc[1]);
        acc[2] = __hfma2(srep, ka[2], acc[2]);
        acc[3] = __hfma2(srep, ka[3], acc[3]);
        acc[4] = __hfma2(srep, kb[0], acc[4]);
        acc[5] = __hfma2(srep, kb[1], acc[5]);
        acc[6] = __hfma2(srep, kb[2], acc[6]);
        acc[7] = __hfma2(srep, kb[3], acc[7]);
    };

    // Rare exact fallback from global (validity-masked, clamped idx)
    auto tap_generic = [&](float y, float x, __half2* acc, int kk) {
        const float y0f = floorf(y), x0f = floorf(x);
        const float wy = y - y0f, wx = x - x0f;
        const int y0 = (int)y0f, x0 = (int)x0f;
        const int y1 = y0 + 1, x1 = x0 + 1;
        const bool vy0 = ((unsigned)y0 < Hc), vy1 = ((unsigned)y1 < Hc);
        const bool vx0 = ((unsigned)x0 < Wc), vx1 = ((unsigned)x1 < Wc);
        const float w00 = (1.0f - wy) * (1.0f - wx) * (float)(vy0 && vx0);
        const float w01 = (1.0f - wy) * wx          * (float)(vy0 && vx1);
        const float w10 = wy          * (1.0f - wx) * (float)(vy1 && vx0);
        const float w11 = wy          * wx          * (float)(vy1 && vx1);
        const int cy0 = min(max(y0, 0), Hc - 1), cy1 = min(max(y1, 0), Hc - 1);
        const int cx0 = min(max(x0, 0), Wc - 1), cx1 = min(max(x1, 0), Wc - 1);
        const int i00 = cy0 * Wc + cx0, i01 = cy0 * Wc + cx1;
        const int i10 = cy1 * Wc + cx0, i11 = cy1 * Wc + cx1;
        const uint4* kwb = (const uint4*)(skwh + (kk * Cc) * 8);
        #pragma unroll
        for (int c = 0; c < Cc; c++) {
            const float* ic = inB + c * HWc;
            const float s = w00 * __ldg(ic + i00) + w01 * __ldg(ic + i01)
                          + w10 * __ldg(ic + i10) + w11 * __ldg(ic + i11);
            acc_channel(acc, __float2half2_rn(s), kwb[2 * c], kwb[2 * c + 1]);
        }
    };

    // Fast-path sampler: bilinear in packed half2 -> sv[8] = (s_2j, s_2j+1)
    auto sample16h = [&](int site, float wy, float wx, __half2* sv) {
        const __half2 h00 = __float2half2_rn((1.0f - wy) * (1.0f - wx));
        const __half2 h01 = __float2half2_rn((1.0f - wy) * wx);
        const __half2 h10 = __float2half2_rn(wy * (1.0f - wx));
        const __half2 h11 = __float2half2_rn(wy * wx);
        const uint4* p = sIn + 2 * site;
        #pragma unroll
        for (int chunk = 0; chunk < 2; chunk++) {
            const uint4 a00 = p[chunk];
            const uint4 a01 = p[2 + chunk];
            const uint4 a10 = p[2 * COLS + chunk];
            const uint4 a11 = p[2 * COLS + 2 + chunk];
            const __half2* c00 = (const __half2*)&a00;
            const __half2* c01 = (const __half2*)&a01;
            const __half2* c10 = (const __half2*)&a10;
            const __half2* c11 = (const __half2*)&a11;
            #pragma unroll
            for (int j = 0; j < 4; j++) {
                __half2 v = __hmul2(c00[j], h00);
                v = __hfma2(c01[j], h01, v);
                v = __hfma2(c10[j], h10, v);
                v = __hfma2(c11[j], h11, v);
                sv[chunk * 4 + j] = v;
            }
        }
    };

    for (int kk = 0; kk < Kc; kk++) {
        const int kr = kk / 3;
        const int kc = kk - 3 * kr;

        const float dya = __ldg(offA  + (2 * kk) * HWc);
        const float dxa = __ldg(offA  + (2 * kk + 1) * HWc);
        const float dyb = __ldg(offBp + (2 * kk) * HWc);
        const float dxb = __ldg(offBp + (2 * kk + 1) * HWc);

        const float ya = dya + (float)(ha - 1 + kr);
        const float xa = dxa + (float)(wpx - 1 + kc);
        const float yb = dyb + (float)(hb - 1 + kr);
        const float xb = dxb + (float)(wpx - 1 + kc);

        const float ya0f = floorf(ya), xa0f = floorf(xa);
        const float yb0f = floorf(yb), xb0f = floorf(xb);
        const float wya = ya - ya0f, wxa = xa - xa0f;
        const float wyb = yb - yb0f, wxb = xb - xb0f;

        const int ry0a = (int)ya0f - rowLo, rx0a = (int)xa0f - colLo;
        const int ry0b = (int)yb0f - rowLo, rx0b = (int)xb0f - colLo;

        const bool fa = ((unsigned)ry0a <= (ROWS - 2)) && ((unsigned)rx0a <= (COLS - 2));
        const bool fb = ((unsigned)ry0b <= (ROWS - 2)) && ((unsigned)rx0b <= (COLS - 2));

        if (fa && fb) {
            __half2 sva[8], svb[8];
            sample16h(ry0a * COLS + rx0a, wya, wxa, sva);
            sample16h(ry0b * COLS + rx0b, wyb, wxb, svb);

            const uint4* kwb = (const uint4*)(skwh + (kk * Cc) * 8);
            #pragma unroll
            for (int cj = 0; cj < 8; cj++) {
                const __half2 alo = __low2half2(sva[cj]);
                const __half2 ahi = __high2half2(sva[cj]);
                const __half2 blo = __low2half2(svb[cj]);
                const __half2 bhi = __high2half2(svb[cj]);
                const uint4 kA0 = kwb[(2 * cj) * 2];
                const uint4 kA1 = kwb[(2 * cj) * 2 + 1];
                const uint4 kB0 = kwb[(2 * cj + 1) * 2];
                const uint4 kB1 = kwb[(2 * cj + 1) * 2 + 1];
                acc_channel(acc_a, alo, kA0, kA1);
                acc_channel(acc_b, blo, kA0, kA1);
                acc_channel(acc_a, ahi, kB0, kB1);
                acc_channel(acc_b, bhi, kB0, kB1);
            }
        } else {
            tap_generic(ya, xa, acc_a, kk);
            tap_generic(yb, xb, acc_b, kk);
        }
    }

    // ---- Squared error vs target for both pixels (fp32) ----
    const float* ta = target + b * Coc * HWc + hwa;
    const float* tb = target + b * Coc * HWc + hwb;
    float local = 0.0f;
    #pragma unroll
    for (int j = 0; j < 8; j++) {
        const float2 fa2 = __half22float2(acc_a[j]);
        float d0 = fa2.x - __ldg(ta + (2 * j) * HWc);
        float d1 = fa2.y - __ldg(ta + (2 * j + 1) * HWc);
        local += d0 * d0 + d1 * d1;
        const float2 fb2 = __half22float2(acc_b[j]);
        d0 = fb2.x - __ldg(tb + (2 * j) * HWc);
        d1 = fb2.y - __ldg(tb + (2 * j + 1) * HWc);
        local += d0 * d0 + d1 * d1;
    }

    // ---- Warp + block reduce, one atomic per block ----
    #pragma unroll
    for (int s = 16; s > 0; s >>= 1)
        local += __shfl_xor_sync(0xFFFFFFFFu, local, s);

    __shared__ float red[8];
    if ((tid & 31) == 0) red[tid >> 5] = local;
    __syncthreads();
    if (tid < 8) {
        float v = red[tid];
        #pragma unroll
        for (int s = 4; s > 0; s >>= 1)
            v += __shfl_xor_sync(0xFFu, v, s);
        if (tid == 0) atomicAdd(out, v * INV_N);
    }
}

extern "C" void kernel_launch(void* const* d_in, const int* in_sizes, int n_in,
                              void* d_out, int out_size) {
    const float* offsets = (const float*)d_in[0];
    const float* input   = (const float*)d_in[1];
    const float* ker     = (const float*)d_in[2];
    const float* target  = (const float*)d_in[3];
    float* out = (float*)d_out;

    static bool attr_set = false;
    if (!attr_set) {
        cudaFuncSetAttribute(dcn_loss_kernel,
                             cudaFuncAttributeMaxDynamicSharedMemorySize,
                             SMEM_BYTES);
        attr_set = true;
    }

    zero_out_kernel<<<1, 32>>>(out);

    dim3 grid(Wc / TILE_W, Hc / TILE_H, Bc);   // 8 x 16 x 4 = 512 blocks
    dcn_loss_kernel<<<grid, 256, SMEM_BYTES>>>(offsets, input, ker, target, out);
}

// round 7
// speedup vs baseline: 1.9775x; 1.2714x over previous
#include <cuda_runtime.h>
#include <cuda_fp16.h>
#include <cuda_bf16.h>

// Problem constants (fixed by the dataset)
#define Bc   4
#define Cc   16
#define Hc   256
#define Wc   256
#define HWc  (Hc * Wc)
#define Coc  16
#define Kc   9
#define INV_N (1.0f / (float)(Bc * Coc * HWc))

// Tiling: 32x32 pixel tile, 256 threads, 4 pixels/thread (rows r+0,8,16,24)
#define TILE_W 32
#define TILE_H 32
#define PAD    6
#define ROWS   (TILE_H + 2 * PAD)     // 44
#define COLS   (TILE_W + 2 * PAD)     // 44
#define NSITES (ROWS * COLS)          // 1936
#define SITE_U4 3                     // 48B per site: 16 fp16 ch + 8 pad halves
#define SIN_BYTES   (NSITES * SITE_U4 * 16)         // 92928
#define SKER_H2     (Kc * Cc * Coc / 2)             // 1152 half2
#define SMEM_BYTES  (SIN_BYTES + SKER_H2 * 4)       // 97536 B

#define NPX 4

__global__ void zero_out_kernel(float* out) {
    if (threadIdx.x == 0) out[0] = 0.0f;
}

extern __shared__ float smem[];

__global__ __launch_bounds__(256, 2) void dcn_loss_kernel(
    const float* __restrict__ offsets,  // [B, 18, H, W]
    const float* __restrict__ input,    // [B, 16, H, W]
    const float* __restrict__ ker,      // [16, 16, 3, 3]
    const float* __restrict__ target,   // [B, 16, H, W]
    float* __restrict__ out)
{
    const int tid = threadIdx.x;
    const int b   = blockIdx.z;
    const int rowBase = blockIdx.y * TILE_H;
    const int colBase = blockIdx.x * TILE_W;
    const int rowLo = rowBase - PAD;
    const int colLo = colBase - PAD;

    const float* inB = input + b * Cc * HWc;
    uint4*   sIn  = (uint4*)smem;                         // SITE_U4 uint4 per site
    __half2* skwh = (__half2*)((char*)smem + SIN_BYTES);  // packed half2 weights

    // ---- Stage input tile as fp16, site-major, 48B stride (zeros outside image) ----
    for (int i = tid; i < NSITES; i += 256) {
        const int ry = i / COLS;
        const int rx = i - ry * COLS;
        const int gy = rowLo + ry;
        const int gx = colLo + rx;
        const bool ok = ((unsigned)gy < Hc) && ((unsigned)gx < Wc);
        const float* src = inB + gy * Wc + gx;
        __half2 h[8];
        #pragma unroll
        for (int j = 0; j < 8; j++) {
            float v0 = ok ? __ldg(src + (2 * j) * HWc)     : 0.0f;
            float v1 = ok ? __ldg(src + (2 * j + 1) * HWc) : 0.0f;
            h[j] = __floats2half2_rn(v0, v1);
        }
        sIn[SITE_U4 * i]     = *(const uint4*)&h[0];
        sIn[SITE_U4 * i + 1] = *(const uint4*)&h[4];
        // chunk 2 is padding, never read
    }

    // ---- Stage weights: skwh[(kk*16 + c)*8 + j] = (w[o=2j], w[o=2j+1]) ----
    for (int i = tid; i < SKER_H2; i += 256) {
        const int j  = i & 7;           // output pair
        const int ck = i >> 3;          // kk*16 + c
        const int kk = ck >> 4;
        const int c  = ck & 15;
        const float w0 = ker[(2 * j)     * (Cc * Kc) + c * Kc + kk];
        const float w1 = ker[(2 * j + 1) * (Cc * Kc) + c * Kc + kk];
        skwh[i] = __floats2half2_rn(w0, w1);
    }
    __syncthreads();

    // ---- Four pixels per thread ----
    const int lane = tid & 31;
    const int r    = tid >> 5;
    const int wpx  = colBase + lane;

    int   hpx[NPX], hw[NPX];
    #pragma unroll
    for (int p = 0; p < NPX; p++) {
        hpx[p] = rowBase + r + 8 * p;
        hw[p]  = hpx[p] * Wc + wpx;
    }
    const float* offBase = offsets + b * 2 * Kc * HWc;
    const float* tgtBase = target  + b * Coc * HWc;

    __half2 acc[NPX][8];                 // acc[p][j] holds outputs (2j, 2j+1)
    #pragma unroll
    for (int p = 0; p < NPX; p++)
        #pragma unroll
        for (int j = 0; j < 8; j++)
            acc[p][j] = __float2half2_rn(0.0f);

    // Accumulate one channel's replicated sample against its 8 weight-half2
    auto acc_channel = [&](__half2* a, __half2 srep, const uint4 k0, const uint4 k1) {
        const __half2* ka = (const __half2*)&k0;
        const __half2* kb = (const __half2*)&k1;
        a[0] = __hfma2(srep, ka[0], a[0]);
        a[1] = __hfma2(srep, ka[1], a[1]);
        a[2] = __hfma2(srep, ka[2], a[2]);
        a[3] = __hfma2(srep, ka[3], a[3]);
        a[4] = __hfma2(srep, kb[0], a[4]);
        a[5] = __hfma2(srep, kb[1], a[5]);
        a[6] = __hfma2(srep, kb[2], a[6]);
        a[7] = __hfma2(srep, kb[3], a[7]);
    };

    // Rare exact fallback from global (validity-masked, clamped idx)
    auto tap_generic = [&](float y, float x, __half2* a, int kk) {
        const float y0f = floorf(y), x0f = floorf(x);
        const float wy = y - y0f, wx = x - x0f;
        const int y0 = (int)y0f, x0 = (int)x0f;
        const int y1 = y0 + 1, x1 = x0 + 1;
        const bool vy0 = ((unsigned)y0 < Hc), vy1 = ((unsigned)y1 < Hc);
        const bool vx0 = ((unsigned)x0 < Wc), vx1 = ((unsigned)x1 < Wc);
        const float w00 = (1.0f - wy) * (1.0f - wx) * (float)(vy0 && vx0);
        const float w01 = (1.0f - wy) * wx          * (float)(vy0 && vx1);
        const float w10 = wy          * (1.0f - wx) * (float)(vy1 && vx0);
        const float w11 = wy          * wx          * (float)(vy1 && vx1);
        const int cy0 = min(max(y0, 0), Hc - 1), cy1 = min(max(y1, 0), Hc - 1);
        const int cx0 = min(max(x0, 0), Wc - 1), cx1 = min(max(x1, 0), Wc - 1);
        const int i00 = cy0 * Wc + cx0, i01 = cy0 * Wc + cx1;
        const int i10 = cy1 * Wc + cx0, i11 = cy1 * Wc + cx1;
        const uint4* kwb = (const uint4*)(skwh + (kk * Cc) * 8);
        #pragma unroll
        for (int c = 0; c < Cc; c++) {
            const float* ic = inB + c * HWc;
            const float s = w00 * __ldg(ic + i00) + w01 * __ldg(ic + i01)
                          + w10 * __ldg(ic + i10) + w11 * __ldg(ic + i11);
            acc_channel(a, __float2half2_rn(s), kwb[2 * c], kwb[2 * c + 1]);
        }
    };

    // Fast-path sampler: bilinear in packed half2 -> sv[8] = (s_2j, s_2j+1)
    auto sample16h = [&](int site, float wy, float wx, __half2* sv) {
        const __half2 h00 = __float2half2_rn((1.0f - wy) * (1.0f - wx));
        const __half2 h01 = __float2half2_rn((1.0f - wy) * wx);
        const __half2 h10 = __float2half2_rn(wy * (1.0f - wx));
        const __half2 h11 = __float2half2_rn(wy * wx);
        const uint4* p = sIn + SITE_U4 * site;
        #pragma unroll
        for (int chunk = 0; chunk < 2; chunk++) {
            const uint4 a00 = p[chunk];
            const uint4 a01 = p[SITE_U4 + chunk];
            const uint4 a10 = p[SITE_U4 * COLS + chunk];
            const uint4 a11 = p[SITE_U4 * COLS + SITE_U4 + chunk];
            const __half2* c00 = (const __half2*)&a00;
            const __half2* c01 = (const __half2*)&a01;
            const __half2* c10 = (const __half2*)&a10;
            const __half2* c11 = (const __half2*)&a11;
            #pragma unroll
            for (int j = 0; j < 4; j++) {
                __half2 v = __hmul2(c00[j], h00);
                v = __hfma2(c01[j], h01, v);
                v = __hfma2(c10[j], h10, v);
                v = __hfma2(c11[j], h11, v);
                sv[chunk * 4 + j] = v;
            }
        }
    };

    for (int kk = 0; kk < Kc; kk++) {
        const int kr = kk / 3;
        const int kc = kk - 3 * kr;

        float yv[NPX], xv[NPX], wyv[NPX], wxv[NPX];
        int   sitev[NPX];
        bool  allfast = true;
        #pragma unroll
        for (int p = 0; p < NPX; p++) {
            const float dy = __ldg(offBase + (2 * kk) * HWc + hw[p]);
            const float dx = __ldg(offBase + (2 * kk + 1) * HWc + hw[p]);
            yv[p] = dy + (float)(hpx[p] - 1 + kr);
            xv[p] = dx + (float)(wpx - 1 + kc);
            const float y0f = floorf(yv[p]);
            const float x0f = floorf(xv[p]);
            wyv[p] = yv[p] - y0f;
            wxv[p] = xv[p] - x0f;
            const int ry0 = (int)y0f - rowLo;
            const int rx0 = (int)x0f - colLo;
            sitev[p] = ry0 * COLS + rx0;
            allfast &= ((unsigned)ry0 <= (ROWS - 2)) && ((unsigned)rx0 <= (COLS - 2));
        }

        if (allfast) {
            __half2 sv[NPX][8];
            #pragma unroll
            for (int p = 0; p < NPX; p++)
                sample16h(sitev[p], wyv[p], wxv[p], sv[p]);

            const uint4* kwb = (const uint4*)(skwh + (kk * Cc) * 8);
            #pragma unroll
            for (int cj = 0; cj < 8; cj++) {
                const uint4 kA0 = kwb[(2 * cj) * 2];
                const uint4 kA1 = kwb[(2 * cj) * 2 + 1];
                const uint4 kB0 = kwb[(2 * cj + 1) * 2];
                const uint4 kB1 = kwb[(2 * cj + 1) * 2 + 1];
                #pragma unroll
                for (int p = 0; p < NPX; p++) {
                    acc_channel(acc[p], __low2half2(sv[p][cj]),  kA0, kA1);
                    acc_channel(acc[p], __high2half2(sv[p][cj]), kB0, kB1);
                }
            }
        } else {
            #pragma unroll
            for (int p = 0; p < NPX; p++)
                tap_generic(yv[p], xv[p], acc[p], kk);
        }
    }

    // ---- Squared error vs target (fp32) ----
    float local = 0.0f;
    #pragma unroll
    for (int p = 0; p < NPX; p++) {
        const float* tg = tgtBase + hw[p];
        #pragma unroll
        for (int j = 0; j < 8; j++) {
            const float2 f2 = __half22float2(acc[p][j]);
            const float d0 = f2.x - __ldg(tg + (2 * j) * HWc);
            const float d1 = f2.y - __ldg(tg + (2 * j + 1) * HWc);
            local += d0 * d0 + d1 * d1;
        }
    }

    // ---- Warp + block reduce, one atomic per block ----
    #pragma unroll
    for (int s = 16; s > 0; s >>= 1)
        local += __shfl_xor_sync(0xFFFFFFFFu, local, s);

    __shared__ float red[8];
    if ((tid & 31) == 0) red[tid >> 5] = local;
    __syncthreads();
    if (tid < 8) {
        float v = red[tid];
        #pragma unroll
        for (int s = 4; s > 0; s >>= 1)
            v += __shfl_xor_sync(0xFFu, v, s);
        if (tid == 0) atomicAdd(out, v * INV_N);
    }
}

extern "C" void kernel_launch(void* const* d_in, const int* in_sizes, int n_in,
                              void* d_out, int out_size) {
    const float* offsets = (const float*)d_in[0];
    const float* input   = (const float*)d_in[1];
    const float* ker     = (const float*)d_in[2];
    const float* target  = (const float*)d_in[3];
    float* out = (float*)d_out;

    static bool attr_set = false;
    if (!attr_set) {
        cudaFuncSetAttribute(dcn_loss_kernel,
                             cudaFuncAttributeMaxDynamicSharedMemorySize,
                             SMEM_BYTES);
        attr_set = true;
    }

    zero_out_kernel<<<1, 32>>>(out);

    dim3 grid(Wc / TILE_W, Hc / TILE_H, Bc);   // 8 x 8 x 4 = 256 blocks
    dcn_loss_kernel<<<grid, 256, SMEM_BYTES>>>(offsets, input, ker, target, out);
}